// round 10
// baseline (speedup 1.0000x reference)
#include <cuda_runtime.h>
#include <cuda_fp16.h>
#include <math.h>

#define CC    10
#define NN    1152
#define DIN   8
#define DOUT  16
#define BB    256

typedef unsigned long long ull;

// fp16 priors [c][b][n][o] (94.4 MB scratch)
__device__ __half g_pri[(size_t)CC * BB * NN * DOUT];

// ---- packed f32x2 helpers (Blackwell FFMA2 — PTX-only) ----
__device__ __forceinline__ ull pack2(float lo, float hi) {
    ull r; asm("mov.b64 %0, {%1, %2};" : "=l"(r) : "f"(lo), "f"(hi)); return r;
}
__device__ __forceinline__ float2 unpack2(ull v) {
    float2 f; asm("mov.b64 {%0, %1}, %2;" : "=f"(f.x), "=f"(f.y) : "l"(v)); return f;
}
__device__ __forceinline__ ull fma2(ull a, ull b, ull c) {
    ull d; asm("fma.rn.f32x2 %0, %1, %2, %3;" : "=l"(d) : "l"(a), "l"(b), "l"(c)); return d;
}
__device__ __forceinline__ ull add2(ull a, ull b) {
    ull d; asm("add.rn.f32x2 %0, %1, %2;" : "=l"(d) : "l"(a), "l"(b)); return d;
}
__device__ __forceinline__ ull h2_to_f32x2(unsigned int h2) {
    ull d;
    asm("{\n\t"
        ".reg .f16 h0, h1;\n\t"
        ".reg .f32 f0, f1;\n\t"
        "mov.b32 {h0, h1}, %1;\n\t"
        "cvt.f32.f16 f0, h0;\n\t"
        "cvt.f32.f16 f1, h1;\n\t"
        "mov.b64 %0, {f0, f1};\n\t"
        "}" : "=l"(d) : "r"(h2));
    return d;
}
// packed f32x2 (lo,hi) -> half2 (lo,hi)
__device__ __forceinline__ unsigned int f32x2_to_h2(ull v) {
    unsigned int r;
    asm("{\n\t"
        ".reg .f32 lo, hi;\n\t"
        "mov.b64 {lo, hi}, %1;\n\t"
        "cvt.rn.f16x2.f32 %0, hi, lo;\n\t"
        "}" : "=r"(r) : "l"(v));
    return r;
}

// ================= Kernel 1: priors GEMM (fp32 W direct) -> g_pri fp16 =================
// grid (CC, 9, 8); 256 threads. Thread owns (node n, o-half oh), loops 32 batch elems.
#define ZB 8
#define BPB (BB / ZB)   // 32 batch elems per block

__global__ __launch_bounds__(256)
void priors_kernel(const float* __restrict__ x, const float* __restrict__ W) {
    const int tid = threadIdx.x;
    const int oh  = tid & 1;                   // o-half: owns o = oh*8 .. oh*8+7
    const int nn  = tid >> 1;                  // 0..127
    const int c   = blockIdx.x;
    const int n   = blockIdx.y * 128 + nn;
    const int b0  = blockIdx.z * BPB;

    // Load this (n, oh) W slice ONCE: 8 i x 8 o = 64 floats -> 32 f32x2 regs.
    ull w2[32];
    {
        const float4* wr = reinterpret_cast<const float4*>(
            W + (((size_t)c * NN + n) * DIN) * DOUT + oh * 8);
#pragma unroll
        for (int i = 0; i < 8; ++i) {
            float4 q0 = wr[i * 4 + 0];
            float4 q1 = wr[i * 4 + 1];
            w2[i * 4 + 0] = pack2(q0.x, q0.y);
            w2[i * 4 + 1] = pack2(q0.z, q0.w);
            w2[i * 4 + 2] = pack2(q1.x, q1.y);
            w2[i * 4 + 3] = pack2(q1.z, q1.w);
        }
    }

    uint4* op = reinterpret_cast<uint4*>(g_pri);

#pragma unroll 2
    for (int bb = 0; bb < BPB; ++bb) {
        const int b = b0 + bb;
        const float4* xr = reinterpret_cast<const float4*>(x + ((size_t)b * NN + n) * DIN);
        float4 v0 = xr[0], v1 = xr[1];
        float xa[8];
        xa[0]=v0.x; xa[1]=v0.y; xa[2]=v0.z; xa[3]=v0.w;
        xa[4]=v1.x; xa[5]=v1.y; xa[6]=v1.z; xa[7]=v1.w;

        ull acc[4] = {0ull, 0ull, 0ull, 0ull};
#pragma unroll
        for (int i = 0; i < 8; ++i) {
            ull xs = pack2(xa[i], xa[i]);
#pragma unroll
            for (int p = 0; p < 4; ++p)
                acc[p] = fma2(xs, w2[i * 4 + p], acc[p]);
        }
        uint4 o;
        o.x = f32x2_to_h2(acc[0]);
        o.y = f32x2_to_h2(acc[1]);
        o.z = f32x2_to_h2(acc[2]);
        o.w = f32x2_to_h2(acc[3]);
        op[((size_t)(c * BB + b) * NN + n) * 2 + oh] = o;
    }
}

// ================= Kernel 2: routing, priors REGISTER-resident =================
// grid (CC, BB); 256 threads (8 warps). Thread owns (node-group g, o-half oh).
// No smem tile: thread's 9 priors octets load coalesced at src[tid + 256k].
#define T3    256
#define NW3   8
#define KPT3  9    // nodes per thread: NN / (T3/2)

__global__ __launch_bounds__(T3, 3)
void routing_kernel(float* __restrict__ out) {
    __shared__ float red[16 * NW3];
    __shared__ float sew[NW3];
    __shared__ __align__(16) float outv[16];

    const int tid  = threadIdx.x;
    const int lane = tid & 31;
    const int wid  = tid >> 5;
    const int oh   = tid & 1;     // owns o = oh*8 .. oh*8+7
    const int c    = blockIdx.x;
    const int b    = blockIdx.y;

    // ---- load this thread's priors into registers (fp16 packed, 36 regs) ----
    // thread tid covers node (tid>>1) + 128k, o-half (tid&1):
    // flat uint4 index = (n*2 + oh) + 512k... = tid + 256*k. Fully coalesced, MLP=9.
    uint4 h[KPT3];
    {
        const uint4* src = reinterpret_cast<const uint4*>(g_pri)
                         + (size_t)(c * BB + b) * NN * 2;
#pragma unroll
        for (int k = 0; k < KPT3; ++k)
            h[k] = src[tid + 256 * k];
    }

    // ---- iter 0: uniform weights -> s = mean over n, squash ----
    {
        ull s2[4] = {0ull, 0ull, 0ull, 0ull};
#pragma unroll
        for (int k = 0; k < KPT3; ++k) {
            s2[0] = add2(s2[0], h2_to_f32x2(h[k].x));
            s2[1] = add2(s2[1], h2_to_f32x2(h[k].y));
            s2[2] = add2(s2[2], h2_to_f32x2(h[k].z));
            s2[3] = add2(s2[3], h2_to_f32x2(h[k].w));
        }
        float s[8];
        {
            float2 a0 = unpack2(s2[0]), a1 = unpack2(s2[1]);
            float2 a2 = unpack2(s2[2]), a3 = unpack2(s2[3]);
            s[0]=a0.x; s[1]=a0.y; s[2]=a1.x; s[3]=a1.y;
            s[4]=a2.x; s[5]=a2.y; s[6]=a3.x; s[7]=a3.y;
        }
        // reduce across node-groups within warp (keep oh bit = lane bit0 distinct)
        for (int m = 2; m < 32; m <<= 1)
#pragma unroll
            for (int j = 0; j < 8; ++j)
                s[j] += __shfl_xor_sync(0xffffffffu, s[j], m);
        if (lane < 2)
#pragma unroll
            for (int j = 0; j < 8; ++j)
                red[(lane * 8 + j) * NW3 + wid] = s[j];
    }
    __syncthreads();
    if (tid < 16) {
        const int o = tid;
        float s = 0.0f;
#pragma unroll
        for (int w = 0; w < NW3; ++w) s += red[o * NW3 + w];
        s *= (1.0f / (float)NN);
        float q = s * s;
        for (int m = 1; m < 16; m <<= 1) q += __shfl_xor_sync(0xffffu, q, m);
        float scale = q / ((1.0f + q) * sqrtf(q));
        outv[o] = scale * s;
    }

    // ---- iterations 1..2: fused agreement + exp + weighted sum ----
    float lg[KPT3];
#pragma unroll
    for (int k = 0; k < KPT3; ++k) lg[k] = 0.0f;

    for (int it = 1; it <= 2; ++it) {
        __syncthreads();
        const ull* ovp = reinterpret_cast<const ull*>(outv) + oh * 4;
        ull ov[4];
#pragma unroll
        for (int j = 0; j < 4; ++j) ov[j] = ovp[j];

        ull sp2[4] = {0ull, 0ull, 0ull, 0ull};
        float se = 0.0f;
#pragma unroll
        for (int k = 0; k < KPT3; ++k) {
            ull p0 = h2_to_f32x2(h[k].x);
            ull p1 = h2_to_f32x2(h[k].y);
            ull p2 = h2_to_f32x2(h[k].z);
            ull p3 = h2_to_f32x2(h[k].w);
            // agreement half-dot (no max pass — exp safe since ||out||<1 bounds logits)
            ull d2 = fma2(p0, ov[0],
                     fma2(p1, ov[1],
                     fma2(p2, ov[2],
                     fma2(p3, ov[3], 0ull))));
            float2 dd = unpack2(d2);
            float d = dd.x + dd.y;
            d += __shfl_xor_sync(0xffffffffu, d, 1);   // combine the two o-halves
            lg[k] += d;
            // unnormalized softmax weight + weighted sum
            float e = __expf(lg[k]);
            se += e;
            ull e2 = pack2(e, e);
            sp2[0] = fma2(e2, p0, sp2[0]);
            sp2[1] = fma2(e2, p1, sp2[1]);
            sp2[2] = fma2(e2, p2, sp2[2]);
            sp2[3] = fma2(e2, p3, sp2[3]);
        }
        float sp[8];
        {
            float2 a0 = unpack2(sp2[0]), a1 = unpack2(sp2[1]);
            float2 a2 = unpack2(sp2[2]), a3 = unpack2(sp2[3]);
            sp[0]=a0.x; sp[1]=a0.y; sp[2]=a1.x; sp[3]=a1.y;
            sp[4]=a2.x; sp[5]=a2.y; sp[6]=a3.x; sp[7]=a3.y;
        }
        // se: full-warp reduce (2x oh redundancy -> exactly 2*true)
        for (int m = 1; m < 32; m <<= 1)
            se += __shfl_xor_sync(0xffffffffu, se, m);
        // sp: reduce across node-groups only (keep oh distinct)
        for (int m = 2; m < 32; m <<= 1)
#pragma unroll
            for (int j = 0; j < 8; ++j)
                sp[j] += __shfl_xor_sync(0xffffffffu, sp[j], m);
        if (lane == 0) sew[wid] = se;
        if (lane < 2)
#pragma unroll
            for (int j = 0; j < 8; ++j)
                red[(lane * 8 + j) * NW3 + wid] = sp[j];
        __syncthreads();

        if (tid < 16) {
            const int o = tid;
            float sps = 0.0f, ses = 0.0f;
#pragma unroll
            for (int w = 0; w < NW3; ++w) {
                sps += red[o * NW3 + w];
                ses += sew[w];
            }
            float s = sps * (2.0f / ses);   // /2 undoes oh redundancy exactly
            float q = s * s;
            for (int m = 1; m < 16; m <<= 1) q += __shfl_xor_sync(0xffffu, q, m);
            float scale = q / ((1.0f + q) * sqrtf(q));
            float o_ = scale * s;
            outv[o] = o_;
            if (it == 2)
                out[((size_t)c * BB + b) * DOUT + o] = o_;
        }
    }
}

extern "C" void kernel_launch(void* const* d_in, const int* in_sizes, int n_in,
                              void* d_out, int out_size) {
    const float* x = (const float*)d_in[0];   // [256,1152,8]
    const float* W = (const float*)d_in[1];   // [10,1152,8,16]
    float* out = (float*)d_out;               // [10,256,1,16]

    dim3 g1(CC, NN / 128, ZB);                // (10, 9, 8)
    priors_kernel<<<g1, 256>>>(x, W);

    dim3 g2(CC, BB);                          // (10, 256)
    routing_kernel<<<g2, T3>>>(out);
}

// round 11
// speedup vs baseline: 1.1955x; 1.1955x over previous
#include <cuda_runtime.h>
#include <cuda_fp16.h>
#include <math.h>

#define CC    10
#define CH    5        // capsules per chunk (scratch holds one chunk)
#define NN    1152
#define DIN   8
#define DOUT  16
#define BB    256

typedef unsigned long long ull;

// fp16 priors scratch for ONE 5-capsule chunk: [c_local][b][n][o] = 47.2 MB.
// Reused in place by the second chunk -> dead dirty lines never hit DRAM.
__device__ __half g_pri[(size_t)CH * BB * NN * DOUT];

// ---- packed f32x2 helpers (Blackwell FFMA2 — PTX-only) ----
__device__ __forceinline__ ull pack2(float lo, float hi) {
    ull r; asm("mov.b64 %0, {%1, %2};" : "=l"(r) : "f"(lo), "f"(hi)); return r;
}
__device__ __forceinline__ float2 unpack2(ull v) {
    float2 f; asm("mov.b64 {%0, %1}, %2;" : "=f"(f.x), "=f"(f.y) : "l"(v)); return f;
}
__device__ __forceinline__ ull fma2(ull a, ull b, ull c) {
    ull d; asm("fma.rn.f32x2 %0, %1, %2, %3;" : "=l"(d) : "l"(a), "l"(b), "l"(c)); return d;
}
__device__ __forceinline__ ull add2(ull a, ull b) {
    ull d; asm("add.rn.f32x2 %0, %1, %2;" : "=l"(d) : "l"(a), "l"(b)); return d;
}
__device__ __forceinline__ ull h2_to_f32x2(unsigned int h2) {
    ull d;
    asm("{\n\t"
        ".reg .f16 h0, h1;\n\t"
        ".reg .f32 f0, f1;\n\t"
        "mov.b32 {h0, h1}, %1;\n\t"
        "cvt.f32.f16 f0, h0;\n\t"
        "cvt.f32.f16 f1, h1;\n\t"
        "mov.b64 %0, {f0, f1};\n\t"
        "}" : "=l"(d) : "r"(h2));
    return d;
}
__device__ __forceinline__ unsigned int f32x2_to_h2(ull v) {
    unsigned int r;
    asm("{\n\t"
        ".reg .f32 lo, hi;\n\t"
        "mov.b64 {lo, hi}, %1;\n\t"
        "cvt.rn.f16x2.f32 %0, hi, lo;\n\t"
        "}" : "=r"(r) : "l"(v));
    return r;
}

// ================= Kernel 1: priors GEMM (fp32 W) -> g_pri fp16 (chunk-local) =================
// grid (CH, 9, 8); 256 threads. Thread owns (node n, o-half oh), loops 32 batch elems.
#define ZB 8
#define BPB (BB / ZB)   // 32 batch elems per block

__global__ __launch_bounds__(256)
void priors_kernel(const float* __restrict__ x, const float* __restrict__ W, int c0) {
    const int tid = threadIdx.x;
    const int oh  = tid & 1;                   // o-half: owns o = oh*8 .. oh*8+7
    const int nn  = tid >> 1;                  // 0..127
    const int cl  = blockIdx.x;                // chunk-local capsule
    const int cg  = c0 + cl;                   // global capsule (for W)
    const int n   = blockIdx.y * 128 + nn;
    const int b0  = blockIdx.z * BPB;

    // Load this (n, oh) W slice ONCE: 8 i x 8 o = 64 floats -> 32 f32x2 regs.
    ull w2[32];
    {
        const float4* wr = reinterpret_cast<const float4*>(
            W + (((size_t)cg * NN + n) * DIN) * DOUT + oh * 8);
#pragma unroll
        for (int i = 0; i < 8; ++i) {
            float4 q0 = wr[i * 4 + 0];
            float4 q1 = wr[i * 4 + 1];
            w2[i * 4 + 0] = pack2(q0.x, q0.y);
            w2[i * 4 + 1] = pack2(q0.z, q0.w);
            w2[i * 4 + 2] = pack2(q1.x, q1.y);
            w2[i * 4 + 3] = pack2(q1.z, q1.w);
        }
    }

    uint4* op = reinterpret_cast<uint4*>(g_pri);

#pragma unroll 2
    for (int bb = 0; bb < BPB; ++bb) {
        const int b = b0 + bb;
        const float4* xr = reinterpret_cast<const float4*>(x + ((size_t)b * NN + n) * DIN);
        float4 v0 = xr[0], v1 = xr[1];
        float xa[8];
        xa[0]=v0.x; xa[1]=v0.y; xa[2]=v0.z; xa[3]=v0.w;
        xa[4]=v1.x; xa[5]=v1.y; xa[6]=v1.z; xa[7]=v1.w;

        ull acc[4] = {0ull, 0ull, 0ull, 0ull};
#pragma unroll
        for (int i = 0; i < 8; ++i) {
            ull xs = pack2(xa[i], xa[i]);
#pragma unroll
            for (int p = 0; p < 4; ++p)
                acc[p] = fma2(xs, w2[i * 4 + p], acc[p]);
        }
        uint4 o;
        o.x = f32x2_to_h2(acc[0]);
        o.y = f32x2_to_h2(acc[1]);
        o.z = f32x2_to_h2(acc[2]);
        o.w = f32x2_to_h2(acc[3]);
        op[((size_t)(cl * BB + b) * NN + n) * 2 + oh] = o;
    }
}

// ================= Kernel 2: routing, priors tile in SMEM (chunk-local) =================
// grid (CH, BB); 256 threads (8 warps). Thread owns (node-group g, o-half oh).
#define T3    256
#define NW3   8
#define KPT3  9    // nodes per thread: NN / (T3/2)

__global__ __launch_bounds__(T3, 4)
void routing_kernel(float* __restrict__ out, int c0) {
    __shared__ __align__(16) __half spri[NN * DOUT];   // 36864 B
    __shared__ float red[16 * NW3];
    __shared__ float sew[NW3];
    __shared__ __align__(16) float outv[16];

    const int tid  = threadIdx.x;
    const int lane = tid & 31;
    const int wid  = tid >> 5;
    const int oh   = tid & 1;     // owns o = oh*8 .. oh*8+7
    const int g    = tid >> 1;    // node group 0..127
    const int cl   = blockIdx.x;  // chunk-local capsule
    const int cg   = c0 + cl;     // global capsule (for out)
    const int b    = blockIdx.y;

    // ---- load priors tile: 2304 x 16B, fully coalesced ----
    {
        const uint4* src = reinterpret_cast<const uint4*>(g_pri) + (size_t)(cl * BB + b) * NN * 2;
        uint4* dst = reinterpret_cast<uint4*>(spri);
#pragma unroll
        for (int t = 0; t < 9; ++t)
            dst[tid + t * T3] = src[tid + t * T3];
    }
    __syncthreads();

    // ---- iter 0: uniform weights -> s = mean over n, squash ----
    {
        ull s2[4] = {0ull, 0ull, 0ull, 0ull};
#pragma unroll
        for (int k = 0; k < KPT3; ++k) {
            const uint4 h = *reinterpret_cast<const uint4*>(&spri[(g + 128 * k) * 16 + oh * 8]);
            s2[0] = add2(s2[0], h2_to_f32x2(h.x));
            s2[1] = add2(s2[1], h2_to_f32x2(h.y));
            s2[2] = add2(s2[2], h2_to_f32x2(h.z));
            s2[3] = add2(s2[3], h2_to_f32x2(h.w));
        }
        float s[8];
        {
            float2 a0 = unpack2(s2[0]), a1 = unpack2(s2[1]);
            float2 a2 = unpack2(s2[2]), a3 = unpack2(s2[3]);
            s[0]=a0.x; s[1]=a0.y; s[2]=a1.x; s[3]=a1.y;
            s[4]=a2.x; s[5]=a2.y; s[6]=a3.x; s[7]=a3.y;
        }
        // reduce across the 16 node-groups within each warp (keep oh bit distinct)
        for (int m = 2; m < 32; m <<= 1)
#pragma unroll
            for (int j = 0; j < 8; ++j)
                s[j] += __shfl_xor_sync(0xffffffffu, s[j], m);
        if (lane < 2)
#pragma unroll
            for (int j = 0; j < 8; ++j)
                red[(lane * 8 + j) * NW3 + wid] = s[j];
    }
    __syncthreads();
    if (tid < 16) {
        const int o = tid;
        float s = 0.0f;
#pragma unroll
        for (int w = 0; w < NW3; ++w) s += red[o * NW3 + w];
        s *= (1.0f / (float)NN);
        float q = s * s;
        for (int m = 1; m < 16; m <<= 1) q += __shfl_xor_sync(0xffffu, q, m);
        float scale = q / ((1.0f + q) * sqrtf(q));
        outv[o] = scale * s;
    }

    // ---- iterations 1..2: fused agreement + exp + weighted sum ----
    float lg[KPT3];
#pragma unroll
    for (int k = 0; k < KPT3; ++k) lg[k] = 0.0f;

    for (int it = 1; it <= 2; ++it) {
        __syncthreads();
        const ull* ovp = reinterpret_cast<const ull*>(outv) + oh * 4;
        ull ov[4];
#pragma unroll
        for (int j = 0; j < 4; ++j) ov[j] = ovp[j];

        ull sp2[4] = {0ull, 0ull, 0ull, 0ull};
        float se = 0.0f;
#pragma unroll
        for (int k = 0; k < KPT3; ++k) {
            const uint4 h = *reinterpret_cast<const uint4*>(&spri[(g + 128 * k) * 16 + oh * 8]);
            ull p0 = h2_to_f32x2(h.x);
            ull p1 = h2_to_f32x2(h.y);
            ull p2 = h2_to_f32x2(h.z);
            ull p3 = h2_to_f32x2(h.w);
            // agreement half-dot (no max pass — exp safe since ||out||<1 bounds logits)
            ull d2 = fma2(p0, ov[0],
                     fma2(p1, ov[1],
                     fma2(p2, ov[2],
                     fma2(p3, ov[3], 0ull))));
            float2 dd = unpack2(d2);
            float d = dd.x + dd.y;
            d += __shfl_xor_sync(0xffffffffu, d, 1);   // combine the two o-halves
            lg[k] += d;
            // unnormalized softmax weight + weighted sum
            float e = __expf(lg[k]);
            se += e;
            ull e2 = pack2(e, e);
            sp2[0] = fma2(e2, p0, sp2[0]);
            sp2[1] = fma2(e2, p1, sp2[1]);
            sp2[2] = fma2(e2, p2, sp2[2]);
            sp2[3] = fma2(e2, p3, sp2[3]);
        }
        float sp[8];
        {
            float2 a0 = unpack2(sp2[0]), a1 = unpack2(sp2[1]);
            float2 a2 = unpack2(sp2[2]), a3 = unpack2(sp2[3]);
            sp[0]=a0.x; sp[1]=a0.y; sp[2]=a1.x; sp[3]=a1.y;
            sp[4]=a2.x; sp[5]=a2.y; sp[6]=a3.x; sp[7]=a3.y;
        }
        // se: full-warp reduce (2x oh redundancy -> exactly 2*true)
        for (int m = 1; m < 32; m <<= 1)
            se += __shfl_xor_sync(0xffffffffu, se, m);
        // sp: reduce across node-groups only (keep oh distinct)
        for (int m = 2; m < 32; m <<= 1)
#pragma unroll
            for (int j = 0; j < 8; ++j)
                sp[j] += __shfl_xor_sync(0xffffffffu, sp[j], m);
        if (lane == 0) sew[wid] = se;
        if (lane < 2)
#pragma unroll
            for (int j = 0; j < 8; ++j)
                red[(lane * 8 + j) * NW3 + wid] = sp[j];
        __syncthreads();

        if (tid < 16) {
            const int o = tid;
            float sps = 0.0f, ses = 0.0f;
#pragma unroll
            for (int w = 0; w < NW3; ++w) {
                sps += red[o * NW3 + w];
                ses += sew[w];
            }
            float s = sps * (2.0f / ses);   // /2 undoes oh redundancy exactly
            float q = s * s;
            for (int m = 1; m < 16; m <<= 1) q += __shfl_xor_sync(0xffffu, q, m);
            float scale = q / ((1.0f + q) * sqrtf(q));
            float o_ = scale * s;
            outv[o] = o_;
            if (it == 2)
                out[((size_t)cg * BB + b) * DOUT + o] = o_;
        }
    }
}

extern "C" void kernel_launch(void* const* d_in, const int* in_sizes, int n_in,
                              void* d_out, int out_size) {
    const float* x = (const float*)d_in[0];   // [256,1152,8]
    const float* W = (const float*)d_in[1];   // [10,1152,8,16]
    float* out = (float*)d_out;               // [10,256,1,16]

    dim3 gp(CH, NN / 128, ZB);                // (5, 9, 8)
    dim3 gr(CH, BB);                          // (5, 256)

    // Chunked pipeline: each 47MB priors chunk is written to L2, consumed by the
    // next kernel, then OVERWRITTEN in place by the following chunk -> the
    // scratch round-trip never touches DRAM.
    priors_kernel<<<gp, 256>>>(x, W, 0);
    routing_kernel<<<gr, T3>>>(out, 0);
    priors_kernel<<<gp, 256>>>(x, W, CH);
    routing_kernel<<<gr, T3>>>(out, CH);
}